// round 6
// baseline (speedup 1.0000x reference)
#include <cuda_runtime.h>
#include <math.h>

#define SEQ 2048
#define BAT 128
#define INP 128
#define HID 128
#define GATES 512   // 4*HID

// 512 MB scratch for the precomputed input contribution xg[s][b][g]
__device__ float g_xg[(size_t)SEQ * BAT * GATES];

// ---------------------------------------------------------------------------
// Packed fp32x2 helpers (Blackwell).
// ---------------------------------------------------------------------------
__device__ __forceinline__ void fma2(unsigned long long& d,
                                     unsigned long long a,
                                     unsigned long long b) {
    asm("fma.rn.f32x2 %0, %1, %2, %0;" : "+l"(d) : "l"(a), "l"(b));
}
__device__ __forceinline__ unsigned long long add2(unsigned long long a,
                                                   unsigned long long b) {
    unsigned long long r;
    asm("add.rn.f32x2 %0, %1, %2;" : "=l"(r) : "l"(a), "l"(b));
    return r;
}
__device__ __forceinline__ float2 unpack2(unsigned long long v) {
    float2 r;
    asm("mov.b64 {%0, %1}, %2;" : "=f"(r.x), "=f"(r.y) : "l"(v));
    return r;
}
__device__ __forceinline__ unsigned long long pack2(float lo, float hi) {
    unsigned long long r;
    asm("mov.b64 %0, {%1, %2};" : "=l"(r) : "f"(lo), "f"(hi));
    return r;
}
__device__ __forceinline__ unsigned long long dup2(float v) {
    unsigned long long r;
    asm("mov.b64 %0, {%1, %1};" : "=l"(r) : "f"(v));
    return r;
}

// Fast activations: MUFU-based, no libm branches. err ~1e-6 rel.
__device__ __forceinline__ float fsig(float x) {
    float e = __expf(-x);
    return __fdividef(1.0f, 1.0f + e);
}
__device__ __forceinline__ float ftanh(float x) {
    float ax = fabsf(x);
    float e  = __expf(-2.0f * ax);
    float r  = __fdividef(1.0f - e, 1.0f + e);
    return copysignf(r, x);
}

// ---------------------------------------------------------------------------
// Kernel A: xg[m][g] = sum_k x[m][k] * V[g][k] + b[g] + b2[g]
// (unchanged from the passing round-4 version except unroll 8)
// ---------------------------------------------------------------------------
__global__ __launch_bounds__(256, 2) void xg_kernel(
    const float* __restrict__ x, const float* __restrict__ V,
    const float* __restrict__ b1, const float* __restrict__ b2,
    float* __restrict__ xg)
{
    extern __shared__ unsigned char smraw[];
    float*  As = reinterpret_cast<float*>(smraw);                 // [128][64] f32, 32 KB
    float2* Bs = reinterpret_cast<float2*>(smraw + 128 * 64 * 4); // [128][64] f32x2, 64 KB

    const int tid = threadIdx.x;
    const int m0 = blockIdx.x * 64;
    const int n0 = blockIdx.y * 128;

#pragma unroll
    for (int i = 0; i < 8; i++) {
        int idx = tid + i * 256;
        int row = idx & 63;
        int k4  = (idx >> 6) << 2;
        float4 xv = *reinterpret_cast<const float4*>(x + (size_t)(m0 + row) * INP + k4);
        As[(k4 + 0) * 64 + row] = xv.x;
        As[(k4 + 1) * 64 + row] = xv.y;
        As[(k4 + 2) * 64 + row] = xv.z;
        As[(k4 + 3) * 64 + row] = xv.w;
    }
#pragma unroll
    for (int i = 0; i < 8; i++) {
        int idx = tid + i * 256;
        int p  = idx & 63;
        int k4 = (idx >> 6) << 2;
        float4 v0 = *reinterpret_cast<const float4*>(V + (size_t)(n0 + 2 * p) * INP + k4);
        float4 v1 = *reinterpret_cast<const float4*>(V + (size_t)(n0 + 2 * p + 1) * INP + k4);
        Bs[(k4 + 0) * 64 + p] = make_float2(v0.x, v1.x);
        Bs[(k4 + 1) * 64 + p] = make_float2(v0.y, v1.y);
        Bs[(k4 + 2) * 64 + p] = make_float2(v0.z, v1.z);
        Bs[(k4 + 3) * 64 + p] = make_float2(v0.w, v1.w);
    }
    __syncthreads();

    const int tx = tid & 15;
    const int ty = tid >> 4;
    const int mb = ty * 4, pb = tx * 4;

    unsigned long long acc[4][4];
#pragma unroll
    for (int i = 0; i < 4; i++)
#pragma unroll
        for (int j = 0; j < 4; j++) acc[i][j] = 0ULL;

#pragma unroll 8
    for (int k = 0; k < 128; k++) {
        float4 a = *reinterpret_cast<const float4*>(&As[k * 64 + mb]);
        ulonglong2 bA = *reinterpret_cast<const ulonglong2*>(&Bs[k * 64 + pb]);
        ulonglong2 bB = *reinterpret_cast<const ulonglong2*>(&Bs[k * 64 + pb + 2]);
        unsigned long long ad0 = dup2(a.x), ad1 = dup2(a.y),
                           ad2 = dup2(a.z), ad3 = dup2(a.w);
        fma2(acc[0][0], ad0, bA.x); fma2(acc[0][1], ad0, bA.y);
        fma2(acc[0][2], ad0, bB.x); fma2(acc[0][3], ad0, bB.y);
        fma2(acc[1][0], ad1, bA.x); fma2(acc[1][1], ad1, bA.y);
        fma2(acc[1][2], ad1, bB.x); fma2(acc[1][3], ad1, bB.y);
        fma2(acc[2][0], ad2, bA.x); fma2(acc[2][1], ad2, bA.y);
        fma2(acc[2][2], ad2, bB.x); fma2(acc[2][3], ad2, bB.y);
        fma2(acc[3][0], ad3, bA.x); fma2(acc[3][1], ad3, bA.y);
        fma2(acc[3][2], ad3, bB.x); fma2(acc[3][3], ad3, bB.y);
    }

    unsigned long long biasp[4];
#pragma unroll
    for (int j = 0; j < 4; j++) {
        int n = n0 + 2 * (pb + j);
        biasp[j] = pack2(b1[n] + b2[n], b1[n + 1] + b2[n + 1]);
    }

#pragma unroll
    for (int i = 0; i < 4; i++) {
        size_t base = (size_t)(m0 + mb + i) * GATES + n0 + 2 * pb;
        ulonglong2 r0, r1;
        r0.x = add2(acc[i][0], biasp[0]); r0.y = add2(acc[i][1], biasp[1]);
        r1.x = add2(acc[i][2], biasp[2]); r1.y = add2(acc[i][3], biasp[3]);
        *reinterpret_cast<ulonglong2*>(xg + base)     = r0;
        *reinterpret_cast<ulonglong2*>(xg + base + 4) = r1;
    }
}

// ---------------------------------------------------------------------------
// Kernel B: recurrence. One CTA per batch element, 1024 threads (32 warps).
// Thread t: unit j = t>>3, sub = t&7: gp = sub>>1 (0=i,1=f,2=g,3=o),
//           half = sub&1 (k-range [half*64, half*64+64)).
// Gate row g = gp*128 + j; each gate computed by 2 threads (k-halves),
// combined with one shfl_xor(1). All 8 threads of unit j sit in one
// 8-lane group -> gate exchange via 4 shfls within the warp.
// Weights: W[g][half*64 + 0..31] in regs (16 u64 = 32 regs),
//          W[g][half*64 + 32..63] in smem WqS[8][1024] (128 KB),
//          pre-permuted so WqS[c*1024 + t] is this thread's chunk
//          (conflict-free LDS.128).
// Double-buffered h, ONE __syncthreads per step, fast MUFU activations.
// ---------------------------------------------------------------------------
__global__ __launch_bounds__(1024, 1) void lstm_rec_kernel(
    const float* __restrict__ xg, const float* __restrict__ W,
    float* __restrict__ out)
{
    extern __shared__ unsigned char smraw[];
    ulonglong2* WqS = reinterpret_cast<ulonglong2*>(smraw);        // [8][1024] = 128 KB
    float* hs = reinterpret_cast<float*>(smraw + 8 * 1024 * 16);   // [2][128]

    const int t    = threadIdx.x;
    const int bat  = blockIdx.x;
    const int j    = t >> 3;
    const int sub  = t & 7;
    const int gp   = sub >> 1;          // gate type 0..3 (i,f,g,o)
    const int half = sub & 1;           // k-half
    const int g    = gp * HID + j;      // gate row
    const int b8   = (t & 31) & ~7;     // 8-lane unit-group base within warp

    // Register weights: W[g][half*64 + 0..31] -> 16 u64
    unsigned long long wr[16];
    const unsigned long long* Wrow =
        reinterpret_cast<const unsigned long long*>(W + (size_t)g * INP + half * 64);
#pragma unroll
    for (int q = 0; q < 16; q++) wr[q] = Wrow[q];

    // Pre-permuted smem weights: slot tt <- W[g(tt)][half(tt)*64 + 32 + 4c]
#pragma unroll
    for (int c = 0; c < 8; c++) {
        int gt = ((t & 7) >> 1) * HID + (t >> 3);
        int ht = t & 1;
        WqS[c * 1024 + t] = *reinterpret_cast<const ulonglong2*>(
            W + (size_t)gt * INP + ht * 64 + 32 + c * 4);
    }
    if (t < HID) hs[t] = 0.0f;
    __syncthreads();

    float c = 0.0f, h = 0.0f;
    float xg_cur = xg[(size_t)bat * GATES + g];

    for (int s = 0; s < SEQ; s++) {
        float xg_next = 0.0f;
        if (s + 1 < SEQ)
            xg_next = xg[((size_t)(s + 1) * BAT + bat) * GATES + g];

        // this thread's k-half of h: chunks [half*16 .. half*16+15]
        const ulonglong2* h2 =
            reinterpret_cast<const ulonglong2*>(hs + (s & 1) * HID) + half * 16;

        unsigned long long a0 = 0ULL, a1 = 0ULL, a2 = 0ULL, a3 = 0ULL;
        // k-offset [0..31]: register weights
#pragma unroll
        for (int q = 0; q < 8; q += 2) {
            ulonglong2 hA = h2[q];
            ulonglong2 hB = h2[q + 1];
            fma2(a0, hA.x, wr[2 * q + 0]);
            fma2(a1, hA.y, wr[2 * q + 1]);
            fma2(a2, hB.x, wr[2 * q + 2]);
            fma2(a3, hB.y, wr[2 * q + 3]);
        }
        // k-offset [32..63]: smem weights
#pragma unroll
        for (int q = 0; q < 8; q++) {
            ulonglong2 hv = h2[8 + q];
            ulonglong2 wv = WqS[q * 1024 + t];
            if (q & 1) { fma2(a2, hv.x, wv.x); fma2(a3, hv.y, wv.y); }
            else       { fma2(a0, hv.x, wv.x); fma2(a1, hv.y, wv.y); }
        }
        float2 p0 = unpack2(a0), p1 = unpack2(a1),
               p2 = unpack2(a2), p3 = unpack2(a3);
        float part = ((p0.x + p0.y) + (p1.x + p1.y)) +
                     ((p2.x + p2.y) + (p3.x + p3.y));
        // combine the two k-halves
        float full = part + __shfl_xor_sync(0xffffffffu, part, 1);
        float gate = full + xg_cur;
        xg_cur = xg_next;

        // own activation (duplicated across the half-pair)
        float act = (gp == 2) ? ftanh(gate) : fsig(gate);

        float vi = __shfl_sync(0xffffffffu, act, b8 + 0);
        float vf = __shfl_sync(0xffffffffu, act, b8 + 2);
        float vg = __shfl_sync(0xffffffffu, act, b8 + 4);
        float vo = __shfl_sync(0xffffffffu, act, b8 + 6);

        c = vf * c + vi * vg;
        h = vo * ftanh(c);

        if (sub == 0) hs[((s + 1) & 1) * HID + j] = h;
        if (sub == 2) out[((size_t)s * BAT + bat) * HID + j] = h;
        __syncthreads();
    }

    if (sub == 0) {
        size_t off = (size_t)SEQ * BAT * HID;
        out[off + (size_t)bat * HID + j] = h;                           // h_T
    }
    if (sub == 4) {
        size_t off = (size_t)SEQ * BAT * HID;
        out[off + (size_t)BAT * HID + (size_t)bat * HID + j] = c;       // c_T
    }
}

// ---------------------------------------------------------------------------
extern "C" void kernel_launch(void* const* d_in, const int* in_sizes, int n_in,
                              void* d_out, int out_size) {
    (void)in_sizes; (void)n_in; (void)out_size;
    const float* x  = (const float*)d_in[0];
    const float* V  = (const float*)d_in[1];
    const float* W  = (const float*)d_in[2];
    const float* b  = (const float*)d_in[3];
    const float* b2 = (const float*)d_in[4];
    float* out = (float*)d_out;

    float* xg = nullptr;
    cudaGetSymbolAddress((void**)&xg, g_xg);

    cudaFuncSetAttribute(xg_kernel, cudaFuncAttributeMaxDynamicSharedMemorySize,
                         96 * 1024);
    const int smemB = 8 * 1024 * 16 + 2 * HID * 4 + 256;
    cudaFuncSetAttribute(lstm_rec_kernel, cudaFuncAttributeMaxDynamicSharedMemorySize,
                         smemB);

    dim3 gridA(SEQ * BAT / 64, GATES / 128);
    xg_kernel<<<gridA, 256, 96 * 1024>>>(x, V, b, b2, xg);
    lstm_rec_kernel<<<BAT, 1024, smemB>>>(xg, W, out);
}

// round 7
// speedup vs baseline: 1.3493x; 1.3493x over previous
#include <cuda_runtime.h>
#include <math.h>

#define SEQ 2048
#define BAT 128
#define INP 128
#define HID 128
#define GATES 512   // 4*HID

// 512 MB scratch for the precomputed input contribution xg[s][b][g]
__device__ float g_xg[(size_t)SEQ * BAT * GATES];

// ---------------------------------------------------------------------------
// Packed fp32x2 helpers (Blackwell).
// ---------------------------------------------------------------------------
__device__ __forceinline__ void fma2(unsigned long long& d,
                                     unsigned long long a,
                                     unsigned long long b) {
    asm("fma.rn.f32x2 %0, %1, %2, %0;" : "+l"(d) : "l"(a), "l"(b));
}
__device__ __forceinline__ float2 unpack2(unsigned long long v) {
    float2 r;
    asm("mov.b64 {%0, %1}, %2;" : "=f"(r.x), "=f"(r.y) : "l"(v));
    return r;
}
__device__ __forceinline__ unsigned long long dup2(float v) {
    unsigned long long r;
    asm("mov.b64 %0, {%1, %1};" : "=l"(r) : "f"(v));
    return r;
}

// Fast activations: MUFU-based, no libm branches. err ~1e-6 rel.
__device__ __forceinline__ float fsig(float x) {
    float e = __expf(-x);
    return __fdividef(1.0f, 1.0f + e);
}
__device__ __forceinline__ float ftanh(float x) {
    float ax = fabsf(x);
    float e  = __expf(-2.0f * ax);
    float r  = __fdividef(1.0f - e, 1.0f + e);
    return copysignf(r, x);
}

// ---------------------------------------------------------------------------
// Kernel A: xg[m][g] = sum_k x[m][k] * V[g][k] + b[g] + b2[g]
// M = 262144, N = 512, K = 128 (single K tile).
// CTA tile 128m x 128n, 512 threads, per-thread 8m x 4n.
// A fetched as {m,m+1} f32x2 pairs via warp-broadcast LDS.128 (1 cyc),
// B as one consecutive float4 per lane (conflict-free), b-values dup'd.
// Accumulators packed along m: acc[4 m-pairs][4 n] u64 = 32 regs.
// smem 128 KB -> 1 CTA/SM, FMA-pipe-bound.
// ---------------------------------------------------------------------------
__global__ __launch_bounds__(512, 1) void xg_kernel(
    const float* __restrict__ x, const float* __restrict__ V,
    const float* __restrict__ b1, const float* __restrict__ b2,
    float* __restrict__ xg)
{
    extern __shared__ unsigned char smraw[];
    float* As = reinterpret_cast<float*>(smraw);   // [128k][128m] 64 KB
    float* Bs = As + 128 * 128;                    // [128k][128n] 64 KB

    const int tid = threadIdx.x;
    const int m0 = blockIdx.x * 128;
    const int n0 = blockIdx.y * 128;

    // As[k][m] = x[m0+m][k]   (lanes along m -> conflict-free STS.32)
#pragma unroll
    for (int i = 0; i < 8; i++) {
        int idx = tid + i * 512;          // 0..4095
        int row = idx & 127;              // m
        int k4  = (idx >> 7) << 2;        // 0,4,...,124
        float4 v = *reinterpret_cast<const float4*>(x + (size_t)(m0 + row) * INP + k4);
        As[(k4 + 0) * 128 + row] = v.x;
        As[(k4 + 1) * 128 + row] = v.y;
        As[(k4 + 2) * 128 + row] = v.z;
        As[(k4 + 3) * 128 + row] = v.w;
    }
    // Bs[k][n] = V[n0+n][k]
#pragma unroll
    for (int i = 0; i < 8; i++) {
        int idx = tid + i * 512;
        int row = idx & 127;              // n
        int k4  = (idx >> 7) << 2;
        float4 v = *reinterpret_cast<const float4*>(V + (size_t)(n0 + row) * INP + k4);
        Bs[(k4 + 0) * 128 + row] = v.x;
        Bs[(k4 + 1) * 128 + row] = v.y;
        Bs[(k4 + 2) * 128 + row] = v.z;
        Bs[(k4 + 3) * 128 + row] = v.w;
    }
    __syncthreads();

    const int ty = tid >> 5;              // 0..15 -> m group (8 rows)
    const int mb = ty * 8;
    const int nb = (tid & 31) * 4;        // n base (4 cols)

    unsigned long long acc[4][4];         // [m-pair][n]
#pragma unroll
    for (int i = 0; i < 4; i++)
#pragma unroll
        for (int j = 0; j < 4; j++) acc[i][j] = 0ULL;

#pragma unroll 8
    for (int k = 0; k < 128; k++) {
        // A: 4 m-pairs = 2 broadcast LDS.128 (all lanes in warp same address)
        ulonglong2 aA = *reinterpret_cast<const ulonglong2*>(As + k * 128 + mb);
        ulonglong2 aB = *reinterpret_cast<const ulonglong2*>(As + k * 128 + mb + 4);
        // B: 4 n values, one consecutive float4 per lane (conflict-free)
        float4 bv = *reinterpret_cast<const float4*>(Bs + k * 128 + nb);
        unsigned long long bd0 = dup2(bv.x), bd1 = dup2(bv.y),
                           bd2 = dup2(bv.z), bd3 = dup2(bv.w);
        fma2(acc[0][0], aA.x, bd0); fma2(acc[0][1], aA.x, bd1);
        fma2(acc[0][2], aA.x, bd2); fma2(acc[0][3], aA.x, bd3);
        fma2(acc[1][0], aA.y, bd0); fma2(acc[1][1], aA.y, bd1);
        fma2(acc[1][2], aA.y, bd2); fma2(acc[1][3], aA.y, bd3);
        fma2(acc[2][0], aB.x, bd0); fma2(acc[2][1], aB.x, bd1);
        fma2(acc[2][2], aB.x, bd2); fma2(acc[2][3], aB.x, bd3);
        fma2(acc[3][0], aB.y, bd0); fma2(acc[3][1], aB.y, bd1);
        fma2(acc[3][2], aB.y, bd2); fma2(acc[3][3], aB.y, bd3);
    }

    float bias[4];
#pragma unroll
    for (int n = 0; n < 4; n++)
        bias[n] = b1[n0 + nb + n] + b2[n0 + nb + n];

    // acc[mp][n]: .x -> m row mb+2mp, .y -> row mb+2mp+1
#pragma unroll
    for (int mp = 0; mp < 4; mp++) {
        float2 c0 = unpack2(acc[mp][0]);
        float2 c1 = unpack2(acc[mp][1]);
        float2 c2 = unpack2(acc[mp][2]);
        float2 c3 = unpack2(acc[mp][3]);
        size_t r0 = (size_t)(m0 + mb + 2 * mp) * GATES + n0 + nb;
        *reinterpret_cast<float4*>(xg + r0) =
            make_float4(c0.x + bias[0], c1.x + bias[1], c2.x + bias[2], c3.x + bias[3]);
        *reinterpret_cast<float4*>(xg + r0 + GATES) =
            make_float4(c0.y + bias[0], c1.y + bias[1], c2.y + bias[2], c3.y + bias[3]);
    }
}

// ---------------------------------------------------------------------------
// Kernel B: recurrence (round-4 structure, the best passing config).
// One CTA per batch element, 512 threads.
// Thread t: unit j = t>>2, gate grp = t&3, gate row g = grp*128+j.
// Quad-shfl gate exchange, ONE __syncthreads per step.
// Weights: W[g][0..95] in regs (48 u64), W[g][96..127] in smem, pre-permuted.
// MUFU activations instead of libm.
// ---------------------------------------------------------------------------
__global__ __launch_bounds__(512, 1) void lstm_rec_kernel(
    const float* __restrict__ xg, const float* __restrict__ W,
    float* __restrict__ out)
{
    extern __shared__ unsigned char smraw[];
    ulonglong2* WqS = reinterpret_cast<ulonglong2*>(smraw);       // [8][512] = 64 KB
    float* hs = reinterpret_cast<float*>(smraw + 8 * 512 * 16);   // [2][128]

    const int t   = threadIdx.x;
    const int bat = blockIdx.x;
    const int j   = t >> 2;
    const int grp = t & 3;
    const int g   = grp * HID + j;      // this thread's gate row
    const int qb  = (t & 31) & ~3;      // quad base lane

    // W[g][0..95] -> 48 u64 registers
    unsigned long long wr[48];
    const unsigned long long* Wrow =
        reinterpret_cast<const unsigned long long*>(W + (size_t)g * INP);
#pragma unroll
    for (int q = 0; q < 48; q++) wr[q] = Wrow[q];

    // Pre-permuted smem weights: slot tt <- W[gate_of(tt)][96 + 4*kq .. +3]
    for (int idx = t; idx < 8 * 512; idx += 512) {
        int kq = idx >> 9;
        int tt = idx & 511;
        int gt = (tt & 3) * HID + (tt >> 2);    // gate row of thread tt
        WqS[kq * 512 + tt] =
            *reinterpret_cast<const ulonglong2*>(W + (size_t)gt * INP + 96 + kq * 4);
    }
    if (t < HID) { hs[t] = 0.0f; }
    __syncthreads();

    float c = 0.0f, h = 0.0f;
    float xg_cur = xg[(size_t)bat * GATES + g];

    for (int s = 0; s < SEQ; s++) {
        // branchless prefetch (clamped index; last iteration re-reads, unused)
        int sn = (s + 1 < SEQ) ? (s + 1) : s;
        float xg_next = xg[((size_t)sn * BAT + bat) * GATES + g];

        const ulonglong2* h2 =
            reinterpret_cast<const ulonglong2*>(hs + (s & 1) * HID);

        unsigned long long a0 = 0ULL, a1 = 0ULL, a2 = 0ULL, a3 = 0ULL;
        // h[0..95] x register weights (24 ulonglong2 h-chunks)
#pragma unroll
        for (int q = 0; q < 24; q += 2) {
            ulonglong2 hA = h2[q];
            ulonglong2 hB = h2[q + 1];
            fma2(a0, hA.x, wr[2 * q + 0]);
            fma2(a1, hA.y, wr[2 * q + 1]);
            fma2(a2, hB.x, wr[2 * q + 2]);
            fma2(a3, hB.y, wr[2 * q + 3]);
        }
        // h[96..127] x smem weights (pre-permuted, conflict-free)
#pragma unroll
        for (int q = 0; q < 8; q++) {
            ulonglong2 hv = h2[24 + q];
            ulonglong2 wv = WqS[q * 512 + t];
            if (q & 1) { fma2(a2, hv.x, wv.x); fma2(a3, hv.y, wv.y); }
            else       { fma2(a0, hv.x, wv.x); fma2(a1, hv.y, wv.y); }
        }
        float2 p0 = unpack2(a0), p1 = unpack2(a1),
               p2 = unpack2(a2), p3 = unpack2(a3);
        float gate = ((p0.x + p0.y) + (p1.x + p1.y)) +
                     ((p2.x + p2.y) + (p3.x + p3.y)) + xg_cur;
        xg_cur = xg_next;

        // own activation: grp 0,1,3 -> sigmoid ; grp 2 -> tanh
        float act = (grp == 2) ? ftanh(gate) : fsig(gate);

        float vi = __shfl_sync(0xffffffffu, act, qb + 0);
        float vf = __shfl_sync(0xffffffffu, act, qb + 1);
        float vg = __shfl_sync(0xffffffffu, act, qb + 2);
        float vo = __shfl_sync(0xffffffffu, act, qb + 3);

        c = vf * c + vi * vg;
        h = vo * ftanh(c);

        if (grp == 0) hs[((s + 1) & 1) * HID + j] = h;
        if (grp == 1) out[((size_t)s * BAT + bat) * HID + j] = h;
        __syncthreads();
    }

    if (grp == 0) {
        size_t off = (size_t)SEQ * BAT * HID;
        out[off + (size_t)bat * HID + j] = h;                           // h_T
    }
    if (grp == 1) {
        size_t off = (size_t)SEQ * BAT * HID;
        out[off + (size_t)BAT * HID + (size_t)bat * HID + j] = c;       // c_T
    }
}

// ---------------------------------------------------------------------------
extern "C" void kernel_launch(void* const* d_in, const int* in_sizes, int n_in,
                              void* d_out, int out_size) {
    (void)in_sizes; (void)n_in; (void)out_size;
    const float* x  = (const float*)d_in[0];
    const float* V  = (const float*)d_in[1];
    const float* W  = (const float*)d_in[2];
    const float* b  = (const float*)d_in[3];
    const float* b2 = (const float*)d_in[4];
    float* out = (float*)d_out;

    float* xg = nullptr;
    cudaGetSymbolAddress((void**)&xg, g_xg);

    cudaFuncSetAttribute(xg_kernel, cudaFuncAttributeMaxDynamicSharedMemorySize,
                         128 * 1024);
    const int smemB = 8 * 512 * 16 + 2 * HID * 4 + 256;
    cudaFuncSetAttribute(lstm_rec_kernel, cudaFuncAttributeMaxDynamicSharedMemorySize,
                         smemB);

    dim3 gridA(SEQ * BAT / 128, GATES / 128);
    xg_kernel<<<gridA, 512, 128 * 1024>>>(x, V, b, b2, xg);
    lstm_rec_kernel<<<BAT, 512, smemB>>>(xg, W, out);
}